// round 7
// baseline (speedup 1.0000x reference)
#include <cuda_runtime.h>
#include <cstdint>

// Problem constants (fixed by the reference).
static constexpr int NU    = 100000;   // users
static constexpr int NI    = 50000;    // items
static constexpr int D     = 64;       // dim
static constexpr int NP    = 3;        // meta-paths
static constexpr int DEG   = 16;
static constexpr int EU    = NU * DEG; // edges per user path (1.6M)
static constexpr int EI    = NI * DEG; // edges per item path (0.8M)
static constexpr int BATCH = 8192;

static constexpr int MAXROWS  = 3 * BATCH;        // 24576 distinct flagged rows max
static constexpr int MAXSLOTS = MAXROWS * NP;     // 73728 (id, path) slots
static constexpr int CAP      = 64;               // max edges per slot bin

// Scratch (static device memory; ~58 MB total).
__device__ float              g_agg[(size_t)MAXSLOTS * D];    // 18.9 MB (compact)
__device__ unsigned long long g_bin[(size_t)MAXSLOTS * CAP];  // 37.7 MB (compact)
__device__ int                g_cnt[MAXSLOTS];                // 295 KB
__device__ int                g_rowid[NU + NI];               // 600 KB (-1 = not live)
__device__ int                g_live[MAXROWS];                // r | (item<<30)
__device__ int                g_nlive;

static inline unsigned cdiv(long long a, long long b) { return (unsigned)((a + b - 1) / b); }

// ---------------------------------------------------------------------------
// K0: clear rowid map, bin cursors, live counter
// ---------------------------------------------------------------------------
__global__ void __launch_bounds__(256) k_clear() {
    int t = blockIdx.x * blockDim.x + threadIdx.x;
    if (t < NU + NI) g_rowid[t] = -1;
    int c = t - (NU + NI);
    if (c >= 0 && c < MAXSLOTS) g_cnt[c] = 0;
    if (t == 0) g_nlive = 0;
}

// ---------------------------------------------------------------------------
// K1: flag rows + assign compact ids (CAS-claim, winner takes an id)
// ---------------------------------------------------------------------------
__global__ void __launch_bounds__(256) k_flags(const int* __restrict__ ui,
                                               const int* __restrict__ ii,
                                               const int* __restrict__ ni) {
    int t = blockIdx.x * blockDim.x + threadIdx.x;
    int rg, tag;
    if (t < BATCH)          { rg = ui[t];                tag = 0; }
    else if (t < 2 * BATCH) { rg = NU + ii[t - BATCH];   tag = 1 << 30; }
    else if (t < 3 * BATCH) { rg = NU + ni[t - 2*BATCH]; tag = 1 << 30; }
    else return;

    if (atomicCAS(&g_rowid[rg], -1, -2) == -1) {
        int id = atomicAdd(&g_nlive, 1);
        g_live[id] = (tag ? (rg - NU) : rg) | tag;
        g_rowid[rg] = id;
    }
}

// ---------------------------------------------------------------------------
// K2: bin pass.  4 edges per thread: one LDG.128 of rows, 4 independent rowid
//     gathers (MLP=4), survivor-only cols/vals + atomic cursor + 8B bin store.
// ---------------------------------------------------------------------------
__global__ void __launch_bounds__(256) k_bin(const int*   __restrict__ u_rows,
                                             const int*   __restrict__ u_cols,
                                             const float* __restrict__ u_vals,
                                             const int*   __restrict__ i_rows,
                                             const int*   __restrict__ i_cols,
                                             const float* __restrict__ i_vals) {
    constexpr long long TOTAL4 = (long long)NP * (EU + EI) / 4;   // 1.8M
    long long t = (long long)blockIdx.x * blockDim.x + threadIdx.x;
    if (t >= TOTAL4) return;
    long long e0 = t * 4;

    const int* rows; const int* cols; const float* vals;
    int e, p, roff;
    if (e0 < (long long)NP * EU) {
        e = (int)e0;   p = e / EU;   rows = u_rows; cols = u_cols; vals = u_vals; roff = 0;
    } else {
        e = (int)(e0 - (long long)NP * EU);
        p = e / EI;    rows = i_rows; cols = i_cols; vals = i_vals; roff = NU;
    }

    int4 r4 = __ldg(reinterpret_cast<const int4*>(rows + e));
    // 4 independent gathers into the compact-id map (L2-resident, MLP=4)
    int id0 = g_rowid[roff + r4.x];
    int id1 = g_rowid[roff + r4.y];
    int id2 = g_rowid[roff + r4.z];
    int id3 = g_rowid[roff + r4.w];

    #pragma unroll
    for (int j = 0; j < 4; j++) {
        int id = (j == 0) ? id0 : (j == 1) ? id1 : (j == 2) ? id2 : id3;
        if (id < 0) continue;
        int   c = __ldg(cols + e + j);
        float v = __ldg(vals + e + j);
        int slot = id * NP + p;
        int pos = atomicAdd(&g_cnt[slot], 1);
        if (pos < CAP) {
            unsigned long long pk =
                ((unsigned long long)__float_as_uint(v) << 32) | (unsigned)c;
            g_bin[(size_t)slot * CAP + pos] = pk;
        }
    }
}

// ---------------------------------------------------------------------------
// K3: per-slot reduction.  One warp per live (id,path) slot; register
//     accumulation (float2/lane, 4-way unroll), single 256B store.
// ---------------------------------------------------------------------------
__global__ void __launch_bounds__(128) k_process(const float* __restrict__ u_table,
                                                 const float* __restrict__ i_table) {
    int slot = blockIdx.x * (blockDim.x >> 5) + (threadIdx.x >> 5);
    if (slot >= MAXSLOTS) return;
    int id = slot / NP;
    if (id >= g_nlive) return;
    int lane = threadIdx.x & 31;

    int packed = g_live[id];
    bool item = (packed >> 30) & 1;
    const float* table = item ? i_table : u_table;

    int n = min(g_cnt[slot], CAP);
    const unsigned long long* bin = g_bin + (size_t)slot * CAP;

    float2 acc = {0.f, 0.f};
    int k = 0;
    for (; k + 3 < n; k += 4) {
        unsigned long long pA = __ldg(bin + k);
        unsigned long long pB = __ldg(bin + k + 1);
        unsigned long long pC = __ldg(bin + k + 2);
        unsigned long long pD = __ldg(bin + k + 3);
        float2 tA = __ldg(reinterpret_cast<const float2*>(table + ((size_t)(unsigned)pA & 0x3FFFFFFFu) * D) + lane);
        float2 tB = __ldg(reinterpret_cast<const float2*>(table + ((size_t)(unsigned)pB & 0x3FFFFFFFu) * D) + lane);
        float2 tC = __ldg(reinterpret_cast<const float2*>(table + ((size_t)(unsigned)pC & 0x3FFFFFFFu) * D) + lane);
        float2 tD = __ldg(reinterpret_cast<const float2*>(table + ((size_t)(unsigned)pD & 0x3FFFFFFFu) * D) + lane);
        float vA = __uint_as_float((unsigned)(pA >> 32));
        float vB = __uint_as_float((unsigned)(pB >> 32));
        float vC = __uint_as_float((unsigned)(pC >> 32));
        float vD = __uint_as_float((unsigned)(pD >> 32));
        acc.x += vA * tA.x; acc.y += vA * tA.y;
        acc.x += vB * tB.x; acc.y += vB * tB.y;
        acc.x += vC * tC.x; acc.y += vC * tC.y;
        acc.x += vD * tD.x; acc.y += vD * tD.y;
    }
    for (; k < n; k++) {
        unsigned long long pk = __ldg(bin + k);
        int   c = (int)((unsigned)pk & 0x3FFFFFFFu);
        float v = __uint_as_float((unsigned)(pk >> 32));
        float2 tv = __ldg(reinterpret_cast<const float2*>(table + (size_t)c * D) + lane);
        acc.x += v * tv.x; acc.y += v * tv.y;
    }
    reinterpret_cast<float2*>(g_agg + (size_t)slot * D)[lane] = acc;
}

// ---------------------------------------------------------------------------
// K4: epilogue.  out[seg][b] = relu( sum_p wb[p] * relu( agg[id,p] @ W_p ) )
//     4 rows per warp, 768 blocks.  W in smem packed float2(W[d][c], W[d][c+32])
//     so each matvec step is SHFL + LDS.64 + 2xFFMA.
// ---------------------------------------------------------------------------
__global__ void __launch_bounds__(256) k_out(const float* __restrict__ Wu,
                                             const float* __restrict__ Wi,
                                             const float* __restrict__ wb1,
                                             const float* __restrict__ wb2,
                                             const int*   __restrict__ ui,
                                             const int*   __restrict__ ii,
                                             const int*   __restrict__ ni,
                                             float*       __restrict__ out) {
    __shared__ float2 Ws2[NP * D * 32];          // 49152 B (48 KB exactly)

    constexpr int ROWS_PER_BLOCK = 32;           // 8 warps x 4 rows
    constexpr int BLK_PER_SEG = BATCH / ROWS_PER_BLOCK;  // 256
    int seg = blockIdx.x / BLK_PER_SEG;
    int blk = blockIdx.x % BLK_PER_SEG;

    const float* W    = (seg == 0) ? Wu  : Wi;
    const float* wbp  = (seg == 0) ? wb1 : wb2;
    const int*   idxA = (seg == 0) ? ui : ((seg == 1) ? ii : ni);
    const int    roff = (seg == 0) ? 0 : NU;

    // Pack W: Ws2[p*2048 + d*32 + c] = (W[p][d][c], W[p][d][c+32])
    for (int j = threadIdx.x; j < NP * D * 32; j += blockDim.x) {
        int p = j >> 11, rem = j & 2047, d = rem >> 5, c = rem & 31;
        const float* src = W + p * D * D + d * D + c;
        Ws2[j] = make_float2(__ldg(src), __ldg(src + 32));
    }
    float w0 = __ldg(wbp + 0), w1 = __ldg(wbp + 1), w2 = __ldg(wbp + 2);
    __syncthreads();

    int warp = threadIdx.x >> 5;
    int lane = threadIdx.x & 31;

    #pragma unroll
    for (int i = 0; i < 4; i++) {
        int b = blk * ROWS_PER_BLOCK + warp * 4 + i;
        int idx = __ldg(idxA + b);
        int id = g_rowid[roff + idx];            // compact id (always >= 0)
        const float* base = g_agg + (size_t)(id * NP) * D;
        float accL = 0.f, accH = 0.f;
        #pragma unroll
        for (int p = 0; p < NP; p++) {
            const float* arow = base + p * D;
            float aL = arow[lane];
            float aH = arow[lane + 32];
            float mL = 0.f, mH = 0.f;
            const float2* Wp = Ws2 + p * 2048;
            #pragma unroll
            for (int d = 0; d < 32; d++) {
                float ad = __shfl_sync(0xffffffffu, aL, d);
                float2 w = Wp[d * 32 + lane];
                mL += ad * w.x;
                mH += ad * w.y;
            }
            #pragma unroll
            for (int d = 0; d < 32; d++) {
                float ad = __shfl_sync(0xffffffffu, aH, d);
                float2 w = Wp[(d + 32) * 32 + lane];
                mL += ad * w.x;
                mH += ad * w.y;
            }
            float wp = (p == 0) ? w0 : ((p == 1) ? w1 : w2);
            accL += wp * fmaxf(mL, 0.f);
            accH += wp * fmaxf(mH, 0.f);
        }
        float* o = out + ((size_t)seg * BATCH + b) * D;
        o[lane]      = fmaxf(accL, 0.f);
        o[lane + 32] = fmaxf(accH, 0.f);
    }
}

// ---------------------------------------------------------------------------
// Launch
// ---------------------------------------------------------------------------
extern "C" void kernel_launch(void* const* d_in, const int* in_sizes, int n_in,
                              void* d_out, int out_size) {
    const float* user_table = (const float*)d_in[0];
    const float* item_table = (const float*)d_in[1];
    const float* Wu         = (const float*)d_in[2];
    const float* Wi         = (const float*)d_in[3];
    const float* wb1        = (const float*)d_in[4];
    const float* wb2        = (const float*)d_in[5];
    const float* user_vals  = (const float*)d_in[6];
    const float* item_vals  = (const float*)d_in[7];
    const int*   user_rows  = (const int*)d_in[8];
    const int*   user_cols  = (const int*)d_in[9];
    const int*   item_rows  = (const int*)d_in[10];
    const int*   item_cols  = (const int*)d_in[11];
    const int*   user_idx   = (const int*)d_in[12];
    const int*   item_idx   = (const int*)d_in[13];
    const int*   neg_idx    = (const int*)d_in[14];
    float* out = (float*)d_out;

    k_clear<<<cdiv(NU + NI + MAXSLOTS, 256), 256>>>();
    k_flags<<<cdiv(3 * BATCH, 256), 256>>>(user_idx, item_idx, neg_idx);
    k_bin<<<cdiv((long long)NP * (EU + EI) / 4, 256), 256>>>(user_rows, user_cols, user_vals,
                                                             item_rows, item_cols, item_vals);
    k_process<<<cdiv(MAXSLOTS, 4), 128>>>(user_table, item_table);
    k_out<<<3 * (BATCH / 32), 256>>>(Wu, Wi, wb1, wb2, user_idx, item_idx, neg_idx, out);
}

// round 8
// speedup vs baseline: 1.2246x; 1.2246x over previous
#include <cuda_runtime.h>
#include <cstdint>

// Problem constants (fixed by the reference).
static constexpr int NU    = 100000;   // users
static constexpr int NI    = 50000;    // items
static constexpr int D     = 64;       // dim
static constexpr int NP    = 3;        // meta-paths
static constexpr int DEG   = 16;
static constexpr int EU    = NU * DEG; // edges per user path (1.6M)
static constexpr int EI    = NI * DEG; // edges per item path (0.8M)
static constexpr int BATCH = 8192;

static constexpr int MAXROWS  = 3 * BATCH;        // 24576 distinct flagged rows max
static constexpr int MAXSLOTS = MAXROWS * NP;     // 73728 (id, path) slots
static constexpr int CAP      = 64;               // max edges per slot bin
static constexpr int BMW      = (NU + NI + 31) / 32;  // 4688 bitmap words (18.75 KB)

// Scratch (static device memory; ~58 MB total).
__device__ float              g_agg[(size_t)MAXSLOTS * D];    // 18.9 MB (compact)
__device__ unsigned long long g_bin[(size_t)MAXSLOTS * CAP];  // 37.7 MB (compact)
__device__ int                g_cnt[MAXSLOTS];                // 295 KB
__device__ int                g_rowid[NU + NI];               // 600 KB (-1 = not live)
__device__ unsigned           g_bitmap[BMW];                  // 18.75 KB live-row bits
__device__ int                g_live[MAXROWS];                // r | (item<<30)
__device__ int                g_nlive;

static inline unsigned cdiv(long long a, long long b) { return (unsigned)((a + b - 1) / b); }

// ---------------------------------------------------------------------------
// K0: clear rowid map, bitmap, bin cursors, live counter
// ---------------------------------------------------------------------------
__global__ void __launch_bounds__(256) k_clear() {
    int t = blockIdx.x * blockDim.x + threadIdx.x;
    if (t < NU + NI) g_rowid[t] = -1;
    int b = t - (NU + NI);
    if (b >= 0 && b < BMW) g_bitmap[b] = 0u;
    int c = t - (NU + NI + BMW);
    if (c >= 0 && c < MAXSLOTS) g_cnt[c] = 0;
    if (t == 0) g_nlive = 0;
}

// ---------------------------------------------------------------------------
// K1: flag rows: set bitmap bit + CAS-claim compact id
// ---------------------------------------------------------------------------
__global__ void __launch_bounds__(256) k_flags(const int* __restrict__ ui,
                                               const int* __restrict__ ii,
                                               const int* __restrict__ ni) {
    int t = blockIdx.x * blockDim.x + threadIdx.x;
    int rg, tag;
    if (t < BATCH)          { rg = ui[t];                tag = 0; }
    else if (t < 2 * BATCH) { rg = NU + ii[t - BATCH];   tag = 1 << 30; }
    else if (t < 3 * BATCH) { rg = NU + ni[t - 2*BATCH]; tag = 1 << 30; }
    else return;

    atomicOr(&g_bitmap[rg >> 5], 1u << (rg & 31));
    if (atomicCAS(&g_rowid[rg], -1, -2) == -1) {
        int id = atomicAdd(&g_nlive, 1);
        g_live[id] = (tag ? (rg - NU) : rg) | tag;
        g_rowid[rg] = id;
    }
}

// ---------------------------------------------------------------------------
// K2: bin pass with SMEM bitmap filter.  Each block caches the 18.75 KB
//     live-row bitmap in shared memory; edges are tested via LDS (no L2
//     sector traffic).  Survivors gather compact id + drop (val,col) into
//     the slot bin.  4 edges / thread / iteration (vectorized metadata).
// ---------------------------------------------------------------------------
__global__ void __launch_bounds__(256) k_bin(const int*   __restrict__ u_rows,
                                             const int*   __restrict__ u_cols,
                                             const float* __restrict__ u_vals,
                                             const int*   __restrict__ i_rows,
                                             const int*   __restrict__ i_cols,
                                             const float* __restrict__ i_vals) {
    __shared__ unsigned sbm[BMW];                // 18752 B
    for (int i = threadIdx.x; i < BMW; i += blockDim.x) sbm[i] = g_bitmap[i];
    __syncthreads();

    constexpr long long NG = (long long)NP * (EU + EI) / 4;   // 1.8M groups of 4
    const long long stride = (long long)gridDim.x * blockDim.x;

    for (long long g = (long long)blockIdx.x * blockDim.x + threadIdx.x;
         g < NG; g += stride) {
        long long e0 = g * 4;
        const int* rows; const int* cols; const float* vals;
        int e, p, roff;
        if (e0 < (long long)NP * EU) {
            e = (int)e0;  p = e / EU;
            rows = u_rows; cols = u_cols; vals = u_vals; roff = 0;
        } else {
            e = (int)(e0 - (long long)NP * EU);  p = e / EI;
            rows = i_rows; cols = i_cols; vals = i_vals; roff = NU;
        }

        int4 r4 = __ldg(reinterpret_cast<const int4*>(rows + e));
        int x0 = roff + r4.x, x1 = roff + r4.y, x2 = roff + r4.z, x3 = roff + r4.w;
        unsigned b0 = (sbm[x0 >> 5] >> (x0 & 31)) & 1u;
        unsigned b1 = (sbm[x1 >> 5] >> (x1 & 31)) & 1u;
        unsigned b2 = (sbm[x2 >> 5] >> (x2 & 31)) & 1u;
        unsigned b3 = (sbm[x3 >> 5] >> (x3 & 31)) & 1u;
        if (!(b0 | b1 | b2 | b3)) continue;

        int4   c4 = __ldg(reinterpret_cast<const int4*>(cols + e));
        float4 v4 = __ldg(reinterpret_cast<const float4*>(vals + e));

        if (b0) {
            int slot = g_rowid[x0] * NP + p;
            int pos = atomicAdd(&g_cnt[slot], 1);
            if (pos < CAP)
                g_bin[(size_t)slot * CAP + pos] =
                    ((unsigned long long)__float_as_uint(v4.x) << 32) | (unsigned)c4.x;
        }
        if (b1) {
            int slot = g_rowid[x1] * NP + p;
            int pos = atomicAdd(&g_cnt[slot], 1);
            if (pos < CAP)
                g_bin[(size_t)slot * CAP + pos] =
                    ((unsigned long long)__float_as_uint(v4.y) << 32) | (unsigned)c4.y;
        }
        if (b2) {
            int slot = g_rowid[x2] * NP + p;
            int pos = atomicAdd(&g_cnt[slot], 1);
            if (pos < CAP)
                g_bin[(size_t)slot * CAP + pos] =
                    ((unsigned long long)__float_as_uint(v4.z) << 32) | (unsigned)c4.z;
        }
        if (b3) {
            int slot = g_rowid[x3] * NP + p;
            int pos = atomicAdd(&g_cnt[slot], 1);
            if (pos < CAP)
                g_bin[(size_t)slot * CAP + pos] =
                    ((unsigned long long)__float_as_uint(v4.w) << 32) | (unsigned)c4.w;
        }
    }
}

// ---------------------------------------------------------------------------
// K3: per-slot reduction (round-6 proven version).  One warp per (id,path)
//     slot; register accumulation (float2/lane), single 256B store.
// ---------------------------------------------------------------------------
__global__ void __launch_bounds__(128) k_process(const float* __restrict__ u_table,
                                                 const float* __restrict__ i_table) {
    int slot = blockIdx.x * (blockDim.x >> 5) + (threadIdx.x >> 5);
    if (slot >= MAXSLOTS) return;
    int id = slot / NP;
    if (id >= g_nlive) return;
    int lane = threadIdx.x & 31;

    int packed = g_live[id];
    bool item = (packed >> 30) & 1;
    const float* table = item ? i_table : u_table;

    int n = min(g_cnt[slot], CAP);
    const unsigned long long* bin = g_bin + (size_t)slot * CAP;

    float2 acc = {0.f, 0.f};
    int k = 0;
    for (; k + 1 < n; k += 2) {
        unsigned long long pA = __ldg(bin + k);
        unsigned long long pB = __ldg(bin + k + 1);
        int   cA = (int)((unsigned)pA & 0x3FFFFFFFu);
        int   cB = (int)((unsigned)pB & 0x3FFFFFFFu);
        float vA = __uint_as_float((unsigned)(pA >> 32));
        float vB = __uint_as_float((unsigned)(pB >> 32));
        float2 tA = __ldg(reinterpret_cast<const float2*>(table + (size_t)cA * D) + lane);
        float2 tB = __ldg(reinterpret_cast<const float2*>(table + (size_t)cB * D) + lane);
        acc.x += vA * tA.x; acc.y += vA * tA.y;
        acc.x += vB * tB.x; acc.y += vB * tB.y;
    }
    if (k < n) {
        unsigned long long pk = __ldg(bin + k);
        int   c = (int)((unsigned)pk & 0x3FFFFFFFu);
        float v = __uint_as_float((unsigned)(pk >> 32));
        float2 tv = __ldg(reinterpret_cast<const float2*>(table + (size_t)c * D) + lane);
        acc.x += v * tv.x; acc.y += v * tv.y;
    }
    reinterpret_cast<float2*>(g_agg + (size_t)slot * D)[lane] = acc;
}

// ---------------------------------------------------------------------------
// K4: epilogue (192 blocks, round-6 shape).  float2-packed W in smem:
//     each matvec step = SHFL + LDS.64 + 2xFFMA.  All 6 arow loads prefetched.
// ---------------------------------------------------------------------------
__global__ void __launch_bounds__(256) k_out(const float* __restrict__ Wu,
                                             const float* __restrict__ Wi,
                                             const float* __restrict__ wb1,
                                             const float* __restrict__ wb2,
                                             const int*   __restrict__ ui,
                                             const int*   __restrict__ ii,
                                             const int*   __restrict__ ni,
                                             float*       __restrict__ out) {
    __shared__ float2 Ws2[NP * D * 32];          // 48 KB exactly

    constexpr int ROWS_PER_BLOCK = 128;          // 8 warps x 16 rows
    constexpr int BLK_PER_SEG = BATCH / ROWS_PER_BLOCK;  // 64
    int seg = blockIdx.x / BLK_PER_SEG;
    int blk = blockIdx.x % BLK_PER_SEG;

    const float* W    = (seg == 0) ? Wu  : Wi;
    const float* wbp  = (seg == 0) ? wb1 : wb2;
    const int*   idxA = (seg == 0) ? ui : ((seg == 1) ? ii : ni);
    const int    roff = (seg == 0) ? 0 : NU;

    // Pack W: Ws2[p*2048 + d*32 + c] = (W[p][d][c], W[p][d][c+32])
    for (int j = threadIdx.x; j < NP * D * 32; j += blockDim.x) {
        int p = j >> 11, rem = j & 2047, d = rem >> 5, c = rem & 31;
        const float* src = W + p * D * D + d * D + c;
        Ws2[j] = make_float2(__ldg(src), __ldg(src + 32));
    }
    float w0 = __ldg(wbp + 0), w1 = __ldg(wbp + 1), w2 = __ldg(wbp + 2);
    __syncthreads();

    int warp = threadIdx.x >> 5;
    int lane = threadIdx.x & 31;

    for (int i = 0; i < 16; i++) {
        int b = blk * ROWS_PER_BLOCK + warp * 16 + i;
        int idx = __ldg(idxA + b);
        int id = g_rowid[roff + idx];            // compact id (always >= 0)
        const float* base = g_agg + (size_t)(id * NP) * D;

        // Prefetch all 6 activation halves (MLP=6)
        float aL[NP], aH[NP];
        #pragma unroll
        for (int p = 0; p < NP; p++) {
            aL[p] = base[p * D + lane];
            aH[p] = base[p * D + lane + 32];
        }

        float accL = 0.f, accH = 0.f;
        #pragma unroll
        for (int p = 0; p < NP; p++) {
            float mL = 0.f, mH = 0.f;
            const float2* Wp = Ws2 + p * 2048;
            #pragma unroll
            for (int d = 0; d < 32; d++) {
                float ad = __shfl_sync(0xffffffffu, aL[p], d);
                float2 w = Wp[d * 32 + lane];
                mL += ad * w.x;
                mH += ad * w.y;
            }
            #pragma unroll
            for (int d = 0; d < 32; d++) {
                float ad = __shfl_sync(0xffffffffu, aH[p], d);
                float2 w = Wp[(d + 32) * 32 + lane];
                mL += ad * w.x;
                mH += ad * w.y;
            }
            float wp = (p == 0) ? w0 : ((p == 1) ? w1 : w2);
            accL += wp * fmaxf(mL, 0.f);
            accH += wp * fmaxf(mH, 0.f);
        }
        float* o = out + ((size_t)seg * BATCH + b) * D;
        o[lane]      = fmaxf(accL, 0.f);
        o[lane + 32] = fmaxf(accH, 0.f);
    }
}

// ---------------------------------------------------------------------------
// Launch
// ---------------------------------------------------------------------------
extern "C" void kernel_launch(void* const* d_in, const int* in_sizes, int n_in,
                              void* d_out, int out_size) {
    const float* user_table = (const float*)d_in[0];
    const float* item_table = (const float*)d_in[1];
    const float* Wu         = (const float*)d_in[2];
    const float* Wi         = (const float*)d_in[3];
    const float* wb1        = (const float*)d_in[4];
    const float* wb2        = (const float*)d_in[5];
    const float* user_vals  = (const float*)d_in[6];
    const float* item_vals  = (const float*)d_in[7];
    const int*   user_rows  = (const int*)d_in[8];
    const int*   user_cols  = (const int*)d_in[9];
    const int*   item_rows  = (const int*)d_in[10];
    const int*   item_cols  = (const int*)d_in[11];
    const int*   user_idx   = (const int*)d_in[12];
    const int*   item_idx   = (const int*)d_in[13];
    const int*   neg_idx    = (const int*)d_in[14];
    float* out = (float*)d_out;

    k_clear<<<cdiv(NU + NI + BMW + MAXSLOTS, 256), 256>>>();
    k_flags<<<cdiv(3 * BATCH, 256), 256>>>(user_idx, item_idx, neg_idx);
    k_bin<<<1184, 256>>>(user_rows, user_cols, user_vals,
                         item_rows, item_cols, item_vals);
    k_process<<<cdiv(MAXSLOTS, 4), 128>>>(user_table, item_table);
    k_out<<<3 * (BATCH / 128), 256>>>(Wu, Wi, wb1, wb2, user_idx, item_idx, neg_idx, out);
}